// round 10
// baseline (speedup 1.0000x reference)
#include <cuda_runtime.h>
#include <math.h>

#define NUM_SEQS   64
#define NUM_HEADS  32
#define KVH        8
#define GQ         4      // query heads per kv head
#define HD         128    // head size
#define BS         16     // paged block size
#define MAXL       2048
#define MAXB       128    // max blocks per seq
#define PART       256    // tokens per split-KV partition
#define NP         (MAXL / PART)   // 8
#define NTOK       (PART / NWARPS) // tokens per warp = 32
#define NTHREADS   256
#define NWARPS     8
#define FULLMASK   0xffffffffu

// Split-KV scratch (device globals)
__device__ float g_pacc[NUM_SEQS * KVH * NP * GQ * HD];   // 8.4 MB
__device__ float g_pl[NUM_SEQS * KVH * NP * GQ];

struct AccState {
    float4 a0, a1, a2, a3;
    float  lsum;           // per-lane: sum of e for head (lane&3)
};

// One token: dot for 4 heads -> transposed butterfly (lane l ends with the
// COMPLETE score of head l&3) -> single exp/lane -> broadcast e0..e3 -> V FMA.
__device__ __forceinline__ void token_step(
    AccState& st, const float4 k4, const float4 v4,
    const float4 qr0, const float4 qr1, const float4 qr2, const float4 qr3,
    const float rel, const float slp_lane, const int lane)
{
    float p0 = qr0.x*k4.x + qr0.y*k4.y + qr0.z*k4.z + qr0.w*k4.w;
    float p1 = qr1.x*k4.x + qr1.y*k4.y + qr1.z*k4.z + qr1.w*k4.w;
    float p2 = qr2.x*k4.x + qr2.y*k4.y + qr2.z*k4.z + qr2.w*k4.w;
    float p3 = qr3.x*k4.x + qr3.y*k4.y + qr3.z*k4.z + qr3.w*k4.w;

    // Round 1 (offset 1): pair-swap heads {0,1} and {2,3}
    const bool b0 = (lane & 1);
    float x01 = b0 ? p1 : p0;
    float y01 = b0 ? p0 : p1;
    x01 += __shfl_xor_sync(FULLMASK, y01, 1);
    float x23 = b0 ? p3 : p2;
    float y23 = b0 ? p2 : p3;
    x23 += __shfl_xor_sync(FULLMASK, y23, 1);
    // Round 2 (offset 2): swap head-pairs
    const bool b1 = (lane & 2);
    float x = b1 ? x23 : x01;
    float y = b1 ? x01 : x23;
    x += __shfl_xor_sync(FULLMASK, y, 2);
    // Rounds 3-5: plain butterfly; every lane gets full sum of head (lane&3)
    x += __shfl_xor_sync(FULLMASK, x, 4);
    x += __shfl_xor_sync(FULLMASK, x, 8);
    x += __shfl_xor_sync(FULLMASK, x, 16);

    const float e = __expf(fmaf(slp_lane, rel, x));
    st.lsum += e;

    const float e0 = __shfl_sync(FULLMASK, e, 0);
    const float e1 = __shfl_sync(FULLMASK, e, 1);
    const float e2 = __shfl_sync(FULLMASK, e, 2);
    const float e3 = __shfl_sync(FULLMASK, e, 3);

    st.a0.x += e0*v4.x; st.a0.y += e0*v4.y; st.a0.z += e0*v4.z; st.a0.w += e0*v4.w;
    st.a1.x += e1*v4.x; st.a1.y += e1*v4.y; st.a1.z += e1*v4.z; st.a1.w += e1*v4.w;
    st.a2.x += e2*v4.x; st.a2.y += e2*v4.y; st.a2.z += e2*v4.z; st.a2.w += e2*v4.w;
    st.a3.x += e3*v4.x; st.a3.y += e3*v4.y; st.a3.z += e3*v4.z; st.a3.w += e3*v4.w;
}

// FULL path: software pipeline with prefetch depth 1 (next token pair's
// K/V loads issued before current pair's compute). Row bases precomputed.
__device__ __forceinline__ void run_mainloop_full(
    AccState& st, const float* __restrict__ kcache, const float* __restrict__ vcache,
    const size_t* __restrict__ sbase,
    const float4 qr0, const float4 qr1, const float4 qr2, const float4 qr3,
    const float slp_lane, const float relbase, int warp, int lane)
{
    auto row_of = [&](int tl) -> size_t {
        return sbase[tl >> 4] + (size_t)(tl & 15) * HD;
    };

    const size_t r0 = row_of(warp);
    const size_t r1 = row_of(warp + NWARPS);
    float4 kA = ((const float4*)(kcache + r0))[lane];
    float4 vA = ((const float4*)(vcache + r0))[lane];
    float4 kB = ((const float4*)(kcache + r1))[lane];
    float4 vB = ((const float4*)(vcache + r1))[lane];

    #pragma unroll
    for (int jb = 0; jb < NTOK; jb += 2) {
        const int tlA = warp + jb * NWARPS;
        const int tlB = tlA + NWARPS;

        float4 kA2, vA2, kB2, vB2;
        if (jb < NTOK - 2) {
            const size_t rA = row_of(tlA + 2 * NWARPS);
            const size_t rB = row_of(tlB + 2 * NWARPS);
            kA2 = ((const float4*)(kcache + rA))[lane];
            vA2 = ((const float4*)(vcache + rA))[lane];
            kB2 = ((const float4*)(kcache + rB))[lane];
            vB2 = ((const float4*)(vcache + rB))[lane];
        }

        token_step(st, kA, vA, qr0, qr1, qr2, qr3,
                   relbase + (float)tlA, slp_lane, lane);
        token_step(st, kB, vB, qr0, qr1, qr2, qr3,
                   relbase + (float)tlB, slp_lane, lane);

        kA = kA2; vA = vA2; kB = kB2; vB = vB2;
    }
}

// Partial path (last partition of each sequence): guarded loop.
__device__ __forceinline__ void run_mainloop_partial(
    AccState& st, const float* __restrict__ kcache, const float* __restrict__ vcache,
    const size_t* __restrict__ sbase,
    const float4 qr0, const float4 qr1, const float4 qr2, const float4 qr3,
    const float slp_lane, const float relbase, int warp, int lane, int tmax)
{
    #pragma unroll
    for (int jb = 0; jb < NTOK; jb += 2) {
        const int tlA = warp + jb * NWARPS;
        const int tlB = tlA + NWARPS;
        const bool okA = tlA < tmax;
        const bool okB = tlB < tmax;

        float4 kA, kB, vA, vB;
        if (okA) {
            const size_t rowA = sbase[tlA >> 4] + (size_t)(tlA & 15) * HD;
            kA = ((const float4*)(kcache + rowA))[lane];
            vA = ((const float4*)(vcache + rowA))[lane];
        }
        if (okB) {
            const size_t rowB = sbase[tlB >> 4] + (size_t)(tlB & 15) * HD;
            kB = ((const float4*)(kcache + rowB))[lane];
            vB = ((const float4*)(vcache + rowB))[lane];
        }

        if (okA) token_step(st, kA, vA, qr0, qr1, qr2, qr3,
                            relbase + (float)tlA, slp_lane, lane);
        if (okB) token_step(st, kB, vB, qr0, qr1, qr2, qr3,
                            relbase + (float)tlB, slp_lane, lane);
    }
}

__global__ __launch_bounds__(NTHREADS)
void paged_attn_part_kernel(const float* __restrict__ q,
                            const float* __restrict__ kcache,
                            const float* __restrict__ vcache,
                            const float* __restrict__ scale_p,
                            const int*   __restrict__ btab,
                            const int*   __restrict__ seqlen,
                            const float* __restrict__ slopes)
{
    const int p    = blockIdx.x % NP;
    const int kv   = (blockIdx.x / NP) % KVH;
    const int s    = blockIdx.x / (NP * KVH);
    const int tid  = threadIdx.x;
    const int lane = tid & 31;
    const int warp = tid >> 5;

    const int len = seqlen[s];
    const int t0  = p * PART;
    if (t0 >= len) return;
    const int tmax = min(PART, len - t0);
    const float scale = scale_p[0];

    __shared__ float  red[NWARPS][GQ][HD];   // 16 KB; stages Q at start
    __shared__ float  wl[NWARPS][GQ];
    __shared__ int    blk[PART / BS];        // 16 blocks
    __shared__ size_t sbase[PART / BS];      // precomputed row bases

    for (int i = tid; i < GQ * HD; i += NTHREADS)
        red[0][0][i] = q[(s * NUM_HEADS + kv * GQ) * HD + i] * scale;
    const int nblk = (tmax + BS - 1) >> 4;
    if (tid < nblk) blk[tid] = btab[s * MAXB + (t0 >> 4) + tid];
    __syncthreads();

    const size_t kvbase   = (size_t)kv * BS * HD;
    const size_t kvstride = (size_t)KVH * BS * HD;
    if (tid < nblk) sbase[tid] = (size_t)blk[tid] * kvstride + kvbase;

    const float4 qr0 = ((const float4*)&red[0][0][0])[lane];
    const float4 qr1 = ((const float4*)&red[0][1][0])[lane];
    const float4 qr2 = ((const float4*)&red[0][2][0])[lane];
    const float4 qr3 = ((const float4*)&red[0][3][0])[lane];
    __syncthreads();

    const float slp_lane = slopes[kv * GQ + (lane & 3)];
    const float relbase  = (float)(t0 - (len - 1));

    AccState st;
    st.a0 = make_float4(0,0,0,0); st.a1 = make_float4(0,0,0,0);
    st.a2 = make_float4(0,0,0,0); st.a3 = make_float4(0,0,0,0);
    st.lsum = 0.f;

    if (tmax == PART) {
        run_mainloop_full(st, kcache, vcache, sbase,
                          qr0, qr1, qr2, qr3, slp_lane, relbase, warp, lane);
    } else {
        run_mainloop_partial(st, kcache, vcache, sbase,
                             qr0, qr1, qr2, qr3, slp_lane, relbase, warp, lane, tmax);
    }

    // Cross-warp reduction in smem. Lanes 0-3 hold l sums for heads 0-3.
    if (lane < GQ) wl[warp][lane] = st.lsum;
    ((float4*)&red[warp][0][0])[lane] = st.a0;
    ((float4*)&red[warp][1][0])[lane] = st.a1;
    ((float4*)&red[warp][2][0])[lane] = st.a2;
    ((float4*)&red[warp][3][0])[lane] = st.a3;
    __syncthreads();

    const int d  = tid & 127;
    const int g0 = tid >> 7;
    float r0 = 0.f, r1 = 0.f;
    #pragma unroll
    for (int w = 0; w < NWARPS; w++) {
        r0 += red[w][g0][d];
        r1 += red[w][g0 + 2][d];
    }

    const size_t pb = ((size_t)(s * KVH + kv) * NP + p) * GQ;
    g_pacc[(pb + g0)     * HD + d] = r0;
    g_pacc[(pb + g0 + 2) * HD + d] = r1;
    if (tid < GQ) {
        float L = 0.f;
        #pragma unroll
        for (int w = 0; w < NWARPS; w++) L += wl[w][tid];
        g_pl[pb + tid] = L;
    }
}

// Reduce: 256 threads = 8 warps = 4 heads x 2 partition-chunks.
__global__ __launch_bounds__(256)
void paged_attn_reduce_kernel(const int* __restrict__ seqlen,
                              float* __restrict__ out)
{
    const int s    = blockIdx.x / KVH;
    const int kv   = blockIdx.x % KVH;
    const int wid  = threadIdx.x >> 5;
    const int lane = threadIdx.x & 31;
    const int g    = wid & 3;
    const int c    = wid >> 2;              // 0 or 1

    __shared__ float4 so[2][GQ][32];
    __shared__ float  sl[2][GQ];

    const int len = seqlen[s];
    const int np  = (len + PART - 1) / PART;
    const size_t base = (size_t)(s * KVH + kv) * NP * GQ;

    float4 o = {0,0,0,0};
    float  L = 0.f;
    for (int p = c; p < np; p += 2) {
        const size_t idx = base + (size_t)p * GQ + g;
        const float4 a = ((const float4*)g_pacc)[idx * (HD/4) + lane];
        L += g_pl[idx];
        o.x += a.x; o.y += a.y; o.z += a.z; o.w += a.w;
    }
    so[c][g][lane] = o;
    if (lane == 0) sl[c][g] = L;
    __syncthreads();

    if (wid < GQ) {
        const int gg = wid;
        float4 r = so[0][gg][lane];
        const float4 r1 = so[1][gg][lane];
        r.x += r1.x; r.y += r1.y; r.z += r1.z; r.w += r1.w;
        const float inv = 1.0f / (sl[0][gg] + sl[1][gg]);
        r.x *= inv; r.y *= inv; r.z *= inv; r.w *= inv;
        ((float4*)out)[(size_t)(s * NUM_HEADS + kv * GQ + gg) * (HD/4) + lane] = r;
    }
}

extern "C" void kernel_launch(void* const* d_in, const int* in_sizes, int n_in,
                              void* d_out, int out_size) {
    const float* query       = (const float*)d_in[0];
    const float* key_cache   = (const float*)d_in[1];
    const float* value_cache = (const float*)d_in[2];
    const float* scale       = (const float*)d_in[4];
    const int*   block_tab   = (const int*)  d_in[5];
    const int*   seq_lens    = (const int*)  d_in[6];
    const float* alibi       = (const float*)d_in[9];
    float* out = (float*)d_out;

    paged_attn_part_kernel<<<NUM_SEQS * KVH * NP, NTHREADS>>>(
        query, key_cache, value_cache, scale, block_tab, seq_lens, alibi);
    paged_attn_reduce_kernel<<<NUM_SEQS * KVH, 256>>>(seq_lens, out);
}

// round 11
// speedup vs baseline: 1.0735x; 1.0735x over previous
#include <cuda_runtime.h>
#include <math.h>

#define NUM_SEQS   64
#define NUM_HEADS  32
#define KVH        8
#define GQ         4      // query heads per kv head
#define HD         128    // head size
#define BS         16     // paged block size
#define MAXL       2048
#define MAXB       128    // max blocks per seq
#define PART       128    // tokens per split-KV partition
#define NP         (MAXL / PART)   // 16
#define NTOK       (PART / NWARPS) // 16 tokens per warp
#define NTHREADS   256
#define NWARPS     8
#define FULLMASK   0xffffffffu

// Split-KV scratch (device globals)
__device__ float g_pacc[NUM_SEQS * KVH * NP * GQ * HD];
__device__ float g_pl[NUM_SEQS * KVH * NP * GQ];
__device__ int   g_cnt[NUM_SEQS * KVH];    // zero-initialized; self-cleaning

struct AccState {
    float4 a0, a1, a2, a3;
    float  lsum;           // per-lane: sum of e for head (lane&3)
};

// One token: dot for 4 heads -> transposed butterfly (lane l ends with the
// COMPLETE score of head l&3) -> single exp/lane -> broadcast e0..e3 -> V FMA.
__device__ __forceinline__ void token_step(
    AccState& st, const float4 k4, const float4 v4,
    const float4 qr0, const float4 qr1, const float4 qr2, const float4 qr3,
    const float rel, const float slp_lane, const int lane)
{
    float p0 = qr0.x*k4.x + qr0.y*k4.y + qr0.z*k4.z + qr0.w*k4.w;
    float p1 = qr1.x*k4.x + qr1.y*k4.y + qr1.z*k4.z + qr1.w*k4.w;
    float p2 = qr2.x*k4.x + qr2.y*k4.y + qr2.z*k4.z + qr2.w*k4.w;
    float p3 = qr3.x*k4.x + qr3.y*k4.y + qr3.z*k4.z + qr3.w*k4.w;

    const bool b0 = (lane & 1);
    float x01 = b0 ? p1 : p0;
    float y01 = b0 ? p0 : p1;
    x01 += __shfl_xor_sync(FULLMASK, y01, 1);
    float x23 = b0 ? p3 : p2;
    float y23 = b0 ? p2 : p3;
    x23 += __shfl_xor_sync(FULLMASK, y23, 1);
    const bool b1 = (lane & 2);
    float x = b1 ? x23 : x01;
    float y = b1 ? x01 : x23;
    x += __shfl_xor_sync(FULLMASK, y, 2);
    x += __shfl_xor_sync(FULLMASK, x, 4);
    x += __shfl_xor_sync(FULLMASK, x, 8);
    x += __shfl_xor_sync(FULLMASK, x, 16);

    const float e = __expf(fmaf(slp_lane, rel, x));
    st.lsum += e;

    const float e0 = __shfl_sync(FULLMASK, e, 0);
    const float e1 = __shfl_sync(FULLMASK, e, 1);
    const float e2 = __shfl_sync(FULLMASK, e, 2);
    const float e3 = __shfl_sync(FULLMASK, e, 3);

    st.a0.x += e0*v4.x; st.a0.y += e0*v4.y; st.a0.z += e0*v4.z; st.a0.w += e0*v4.w;
    st.a1.x += e1*v4.x; st.a1.y += e1*v4.y; st.a1.z += e1*v4.z; st.a1.w += e1*v4.w;
    st.a2.x += e2*v4.x; st.a2.y += e2*v4.y; st.a2.z += e2*v4.z; st.a2.w += e2*v4.w;
    st.a3.x += e3*v4.x; st.a3.y += e3*v4.y; st.a3.z += e3*v4.z; st.a3.w += e3*v4.w;
}

// FULL path: software pipeline, prefetch depth 1, precomputed row bases.
__device__ __forceinline__ void run_mainloop_full(
    AccState& st, const float* __restrict__ kcache, const float* __restrict__ vcache,
    const size_t* __restrict__ sbase,
    const float4 qr0, const float4 qr1, const float4 qr2, const float4 qr3,
    const float slp_lane, const float relbase, int warp, int lane)
{
    auto row_of = [&](int tl) -> size_t {
        return sbase[tl >> 4] + (size_t)(tl & 15) * HD;
    };

    const size_t r0 = row_of(warp);
    const size_t r1 = row_of(warp + NWARPS);
    float4 kA = ((const float4*)(kcache + r0))[lane];
    float4 vA = ((const float4*)(vcache + r0))[lane];
    float4 kB = ((const float4*)(kcache + r1))[lane];
    float4 vB = ((const float4*)(vcache + r1))[lane];

    #pragma unroll
    for (int jb = 0; jb < NTOK; jb += 2) {
        const int tlA = warp + jb * NWARPS;
        const int tlB = tlA + NWARPS;

        float4 kA2, vA2, kB2, vB2;
        if (jb < NTOK - 2) {
            const size_t rA = row_of(tlA + 2 * NWARPS);
            const size_t rB = row_of(tlB + 2 * NWARPS);
            kA2 = ((const float4*)(kcache + rA))[lane];
            vA2 = ((const float4*)(vcache + rA))[lane];
            kB2 = ((const float4*)(kcache + rB))[lane];
            vB2 = ((const float4*)(vcache + rB))[lane];
        }

        token_step(st, kA, vA, qr0, qr1, qr2, qr3,
                   relbase + (float)tlA, slp_lane, lane);
        token_step(st, kB, vB, qr0, qr1, qr2, qr3,
                   relbase + (float)tlB, slp_lane, lane);

        kA = kA2; vA = vA2; kB = kB2; vB = vB2;
    }
}

// Partial path (last partition of each sequence): guarded loop.
__device__ __forceinline__ void run_mainloop_partial(
    AccState& st, const float* __restrict__ kcache, const float* __restrict__ vcache,
    const size_t* __restrict__ sbase,
    const float4 qr0, const float4 qr1, const float4 qr2, const float4 qr3,
    const float slp_lane, const float relbase, int warp, int lane, int tmax)
{
    #pragma unroll
    for (int jb = 0; jb < NTOK; jb += 2) {
        const int tlA = warp + jb * NWARPS;
        const int tlB = tlA + NWARPS;
        const bool okA = tlA < tmax;
        const bool okB = tlB < tmax;

        float4 kA, kB, vA, vB;
        if (okA) {
            const size_t rowA = sbase[tlA >> 4] + (size_t)(tlA & 15) * HD;
            kA = ((const float4*)(kcache + rowA))[lane];
            vA = ((const float4*)(vcache + rowA))[lane];
        }
        if (okB) {
            const size_t rowB = sbase[tlB >> 4] + (size_t)(tlB & 15) * HD;
            kB = ((const float4*)(kcache + rowB))[lane];
            vB = ((const float4*)(vcache + rowB))[lane];
        }

        if (okA) token_step(st, kA, vA, qr0, qr1, qr2, qr3,
                            relbase + (float)tlA, slp_lane, lane);
        if (okB) token_step(st, kB, vB, qr0, qr1, qr2, qr3,
                            relbase + (float)tlB, slp_lane, lane);
    }
}

__global__ __launch_bounds__(NTHREADS)
void paged_attn_kernel(const float* __restrict__ q,
                       const float* __restrict__ kcache,
                       const float* __restrict__ vcache,
                       const float* __restrict__ scale_p,
                       const int*   __restrict__ btab,
                       const int*   __restrict__ seqlen,
                       const float* __restrict__ slopes,
                       float*       __restrict__ out)
{
    const int p    = blockIdx.x % NP;
    const int kv   = (blockIdx.x / NP) % KVH;
    const int s    = blockIdx.x / (NP * KVH);
    const int tid  = threadIdx.x;
    const int lane = tid & 31;
    const int warp = tid >> 5;

    const int len = seqlen[s];
    const int t0  = p * PART;
    if (t0 >= len) return;
    const int tmax = min(PART, len - t0);
    const int np   = (len + PART - 1) / PART;   // active partitions
    const float scale = scale_p[0];

    __shared__ float  red[NWARPS][GQ][HD];   // 16 KB; stages Q at start
    __shared__ float  wl[NWARPS][GQ];
    __shared__ int    blk[PART / BS];        // 8 blocks
    __shared__ size_t sbase[PART / BS];
    __shared__ int    is_last;

    for (int i = tid; i < GQ * HD; i += NTHREADS)
        red[0][0][i] = q[(s * NUM_HEADS + kv * GQ) * HD + i] * scale;
    const int nblk = (tmax + BS - 1) >> 4;
    if (tid < nblk) blk[tid] = btab[s * MAXB + (t0 >> 4) + tid];
    __syncthreads();

    const size_t kvbase   = (size_t)kv * BS * HD;
    const size_t kvstride = (size_t)KVH * BS * HD;
    if (tid < nblk) sbase[tid] = (size_t)blk[tid] * kvstride + kvbase;

    const float4 qr0 = ((const float4*)&red[0][0][0])[lane];
    const float4 qr1 = ((const float4*)&red[0][1][0])[lane];
    const float4 qr2 = ((const float4*)&red[0][2][0])[lane];
    const float4 qr3 = ((const float4*)&red[0][3][0])[lane];
    __syncthreads();

    const float slp_lane = slopes[kv * GQ + (lane & 3)];
    const float relbase  = (float)(t0 - (len - 1));

    AccState st;
    st.a0 = make_float4(0,0,0,0); st.a1 = make_float4(0,0,0,0);
    st.a2 = make_float4(0,0,0,0); st.a3 = make_float4(0,0,0,0);
    st.lsum = 0.f;

    if (tmax == PART) {
        run_mainloop_full(st, kcache, vcache, sbase,
                          qr0, qr1, qr2, qr3, slp_lane, relbase, warp, lane);
    } else {
        run_mainloop_partial(st, kcache, vcache, sbase,
                             qr0, qr1, qr2, qr3, slp_lane, relbase, warp, lane, tmax);
    }

    // Cross-warp reduction in smem. Lanes 0-3 hold l sums for heads 0-3.
    if (lane < GQ) wl[warp][lane] = st.lsum;
    ((float4*)&red[warp][0][0])[lane] = st.a0;
    ((float4*)&red[warp][1][0])[lane] = st.a1;
    ((float4*)&red[warp][2][0])[lane] = st.a2;
    ((float4*)&red[warp][3][0])[lane] = st.a3;
    __syncthreads();

    const int d  = tid & 127;
    const int g0 = tid >> 7;
    float r0 = 0.f, r1 = 0.f;
    #pragma unroll
    for (int w = 0; w < NWARPS; w++) {
        r0 += red[w][g0][d];
        r1 += red[w][g0 + 2][d];
    }

    const int    skv = s * KVH + kv;
    const size_t pb  = ((size_t)skv * NP + p) * GQ;
    g_pacc[(pb + g0)     * HD + d] = r0;
    g_pacc[(pb + g0 + 2) * HD + d] = r1;
    if (tid < GQ) {
        float L = 0.f;
        #pragma unroll
        for (int w = 0; w < NWARPS; w++) L += wl[w][tid];
        g_pl[pb + tid] = L;
    }

    // ---- Decoupled completion: last CTA for this (s, kv) combines ----
    __threadfence();            // make partials visible device-wide
    __syncthreads();
    if (tid == 0)
        is_last = (atomicAdd(&g_cnt[skv], 1) == np - 1) ? 1 : 0;
    __syncthreads();
    if (!is_last) return;
    __threadfence();            // acquire: see all CTAs' partials

    const size_t base = (size_t)skv * NP * GQ;
    float L0 = 0.f, L1 = 0.f, o0 = 0.f, o1 = 0.f;
    for (int pp = 0; pp < np; pp++) {
        const size_t i0 = base + (size_t)pp * GQ + g0;
        const size_t i1 = i0 + 2;
        L0 += g_pl[i0];
        L1 += g_pl[i1];
        o0 += g_pacc[i0 * HD + d];
        o1 += g_pacc[i1 * HD + d];
    }
    out[(size_t)(s * NUM_HEADS + kv * GQ + g0)     * HD + d] = o0 / L0;
    out[(size_t)(s * NUM_HEADS + kv * GQ + g0 + 2) * HD + d] = o1 / L1;

    if (tid == 0) g_cnt[skv] = 0;   // self-clean for next (graph) launch
}

extern "C" void kernel_launch(void* const* d_in, const int* in_sizes, int n_in,
                              void* d_out, int out_size) {
    const float* query       = (const float*)d_in[0];
    const float* key_cache   = (const float*)d_in[1];
    const float* value_cache = (const float*)d_in[2];
    const float* scale       = (const float*)d_in[4];
    const int*   block_tab   = (const int*)  d_in[5];
    const int*   seq_lens    = (const int*)  d_in[6];
    const float* alibi       = (const float*)d_in[9];
    float* out = (float*)d_out;

    paged_attn_kernel<<<NUM_SEQS * KVH * NP, NTHREADS>>>(
        query, key_cache, value_cache, scale, block_tab, seq_lens, alibi, out);
}

// round 12
// speedup vs baseline: 1.0789x; 1.0050x over previous
#include <cuda_runtime.h>
#include <math.h>

#define NUM_SEQS   64
#define NUM_HEADS  32
#define KVH        8
#define GQ         4      // query heads per kv head
#define HD         128    // head size
#define BS         16     // paged block size
#define MAXL       2048
#define MAXB       128    // max blocks per seq
#define PART       128    // tokens per split-KV partition
#define NP         (MAXL / PART)   // 16
#define NTOK       (PART / NWARPS) // 16 tokens per warp
#define NTHREADS   256
#define NWARPS     8
#define FULLMASK   0xffffffffu

// Split-KV scratch (device globals)
__device__ float g_pacc[NUM_SEQS * KVH * NP * GQ * HD];
__device__ float g_pl[NUM_SEQS * KVH * NP * GQ];
__device__ int   g_cnt[NUM_SEQS * KVH];    // zero-initialized; self-cleaning

struct AccState {
    float4 a0, a1, a2, a3;
    float  lsum;           // per-lane: sum of e for head (lane&3)
};

// One token: dot for 4 heads -> transposed butterfly (lane l ends with the
// COMPLETE score of head l&3) -> single exp/lane -> broadcast e0..e3 -> V FMA.
__device__ __forceinline__ void token_step(
    AccState& st, const float4 k4, const float4 v4,
    const float4 qr0, const float4 qr1, const float4 qr2, const float4 qr3,
    const float rel, const float slp_lane, const int lane)
{
    float p0 = qr0.x*k4.x + qr0.y*k4.y + qr0.z*k4.z + qr0.w*k4.w;
    float p1 = qr1.x*k4.x + qr1.y*k4.y + qr1.z*k4.z + qr1.w*k4.w;
    float p2 = qr2.x*k4.x + qr2.y*k4.y + qr2.z*k4.z + qr2.w*k4.w;
    float p3 = qr3.x*k4.x + qr3.y*k4.y + qr3.z*k4.z + qr3.w*k4.w;

    const bool b0 = (lane & 1);
    float x01 = b0 ? p1 : p0;
    float y01 = b0 ? p0 : p1;
    x01 += __shfl_xor_sync(FULLMASK, y01, 1);
    float x23 = b0 ? p3 : p2;
    float y23 = b0 ? p2 : p3;
    x23 += __shfl_xor_sync(FULLMASK, y23, 1);
    const bool b1 = (lane & 2);
    float x = b1 ? x23 : x01;
    float y = b1 ? x01 : x23;
    x += __shfl_xor_sync(FULLMASK, y, 2);
    x += __shfl_xor_sync(FULLMASK, x, 4);
    x += __shfl_xor_sync(FULLMASK, x, 8);
    x += __shfl_xor_sync(FULLMASK, x, 16);

    const float e = __expf(fmaf(slp_lane, rel, x));
    st.lsum += e;

    const float e0 = __shfl_sync(FULLMASK, e, 0);
    const float e1 = __shfl_sync(FULLMASK, e, 1);
    const float e2 = __shfl_sync(FULLMASK, e, 2);
    const float e3 = __shfl_sync(FULLMASK, e, 3);

    st.a0.x += e0*v4.x; st.a0.y += e0*v4.y; st.a0.z += e0*v4.z; st.a0.w += e0*v4.w;
    st.a1.x += e1*v4.x; st.a1.y += e1*v4.y; st.a1.z += e1*v4.z; st.a1.w += e1*v4.w;
    st.a2.x += e2*v4.x; st.a2.y += e2*v4.y; st.a2.z += e2*v4.z; st.a2.w += e2*v4.w;
    st.a3.x += e3*v4.x; st.a3.y += e3*v4.y; st.a3.z += e3*v4.z; st.a3.w += e3*v4.w;
}

// FULL path: unguarded 2-token batched loop (no prefetch double-buffer:
// register budget goes to occupancy instead).
__device__ __forceinline__ void run_mainloop_full(
    AccState& st, const float* __restrict__ kcache, const float* __restrict__ vcache,
    const size_t* __restrict__ sbase,
    const float4 qr0, const float4 qr1, const float4 qr2, const float4 qr3,
    const float slp_lane, const float relbase, int warp, int lane)
{
    #pragma unroll
    for (int jb = 0; jb < NTOK; jb += 2) {
        const int tlA = warp + jb * NWARPS;
        const int tlB = tlA + NWARPS;
        const size_t rowA = sbase[tlA >> 4] + (size_t)(tlA & 15) * HD;
        const size_t rowB = sbase[tlB >> 4] + (size_t)(tlB & 15) * HD;
        const float4 kA = ((const float4*)(kcache + rowA))[lane];
        const float4 vA = ((const float4*)(vcache + rowA))[lane];
        const float4 kB = ((const float4*)(kcache + rowB))[lane];
        const float4 vB = ((const float4*)(vcache + rowB))[lane];

        token_step(st, kA, vA, qr0, qr1, qr2, qr3,
                   relbase + (float)tlA, slp_lane, lane);
        token_step(st, kB, vB, qr0, qr1, qr2, qr3,
                   relbase + (float)tlB, slp_lane, lane);
    }
}

// Partial path (last partition of each sequence): guarded loop.
__device__ __forceinline__ void run_mainloop_partial(
    AccState& st, const float* __restrict__ kcache, const float* __restrict__ vcache,
    const size_t* __restrict__ sbase,
    const float4 qr0, const float4 qr1, const float4 qr2, const float4 qr3,
    const float slp_lane, const float relbase, int warp, int lane, int tmax)
{
    #pragma unroll
    for (int jb = 0; jb < NTOK; jb += 2) {
        const int tlA = warp + jb * NWARPS;
        const int tlB = tlA + NWARPS;
        const bool okA = tlA < tmax;
        const bool okB = tlB < tmax;

        float4 kA, kB, vA, vB;
        if (okA) {
            const size_t rowA = sbase[tlA >> 4] + (size_t)(tlA & 15) * HD;
            kA = ((const float4*)(kcache + rowA))[lane];
            vA = ((const float4*)(vcache + rowA))[lane];
        }
        if (okB) {
            const size_t rowB = sbase[tlB >> 4] + (size_t)(tlB & 15) * HD;
            kB = ((const float4*)(kcache + rowB))[lane];
            vB = ((const float4*)(vcache + rowB))[lane];
        }

        if (okA) token_step(st, kA, vA, qr0, qr1, qr2, qr3,
                            relbase + (float)tlA, slp_lane, lane);
        if (okB) token_step(st, kB, vB, qr0, qr1, qr2, qr3,
                            relbase + (float)tlB, slp_lane, lane);
    }
}

__global__ __launch_bounds__(NTHREADS, 4)
void paged_attn_kernel(const float* __restrict__ q,
                       const float* __restrict__ kcache,
                       const float* __restrict__ vcache,
                       const float* __restrict__ scale_p,
                       const int*   __restrict__ btab,
                       const int*   __restrict__ seqlen,
                       const float* __restrict__ slopes,
                       float*       __restrict__ out)
{
    const int p    = blockIdx.x % NP;
    const int kv   = (blockIdx.x / NP) % KVH;
    const int s    = blockIdx.x / (NP * KVH);
    const int tid  = threadIdx.x;
    const int lane = tid & 31;
    const int warp = tid >> 5;

    const int len = seqlen[s];
    const int t0  = p * PART;
    if (t0 >= len) return;
    const int tmax = min(PART, len - t0);
    const int np   = (len + PART - 1) / PART;   // active partitions
    const float scale = scale_p[0];

    __shared__ float  red[NWARPS][GQ][HD];   // 16 KB; stages Q at start
    __shared__ float  wl[NWARPS][GQ];
    __shared__ int    blk[PART / BS];        // 8 blocks
    __shared__ size_t sbase[PART / BS];
    __shared__ int    is_last;

    for (int i = tid; i < GQ * HD; i += NTHREADS)
        red[0][0][i] = q[(s * NUM_HEADS + kv * GQ) * HD + i] * scale;
    const int nblk = (tmax + BS - 1) >> 4;
    if (tid < nblk) blk[tid] = btab[s * MAXB + (t0 >> 4) + tid];
    __syncthreads();

    const size_t kvbase   = (size_t)kv * BS * HD;
    const size_t kvstride = (size_t)KVH * BS * HD;
    if (tid < nblk) sbase[tid] = (size_t)blk[tid] * kvstride + kvbase;

    const float4 qr0 = ((const float4*)&red[0][0][0])[lane];
    const float4 qr1 = ((const float4*)&red[0][1][0])[lane];
    const float4 qr2 = ((const float4*)&red[0][2][0])[lane];
    const float4 qr3 = ((const float4*)&red[0][3][0])[lane];
    __syncthreads();

    const float slp_lane = slopes[kv * GQ + (lane & 3)];
    const float relbase  = (float)(t0 - (len - 1));

    AccState st;
    st.a0 = make_float4(0,0,0,0); st.a1 = make_float4(0,0,0,0);
    st.a2 = make_float4(0,0,0,0); st.a3 = make_float4(0,0,0,0);
    st.lsum = 0.f;

    if (tmax == PART) {
        run_mainloop_full(st, kcache, vcache, sbase,
                          qr0, qr1, qr2, qr3, slp_lane, relbase, warp, lane);
    } else {
        run_mainloop_partial(st, kcache, vcache, sbase,
                             qr0, qr1, qr2, qr3, slp_lane, relbase, warp, lane, tmax);
    }

    // Cross-warp reduction in smem. Lanes 0-3 hold l sums for heads 0-3.
    if (lane < GQ) wl[warp][lane] = st.lsum;
    ((float4*)&red[warp][0][0])[lane] = st.a0;
    ((float4*)&red[warp][1][0])[lane] = st.a1;
    ((float4*)&red[warp][2][0])[lane] = st.a2;
    ((float4*)&red[warp][3][0])[lane] = st.a3;
    __syncthreads();

    const int d  = tid & 127;
    const int g0 = tid >> 7;
    float r0 = 0.f, r1 = 0.f;
    #pragma unroll
    for (int w = 0; w < NWARPS; w++) {
        r0 += red[w][g0][d];
        r1 += red[w][g0 + 2][d];
    }

    const int    skv = s * KVH + kv;
    const size_t pb  = ((size_t)skv * NP + p) * GQ;
    g_pacc[(pb + g0)     * HD + d] = r0;
    g_pacc[(pb + g0 + 2) * HD + d] = r1;
    if (tid < GQ) {
        float L = 0.f;
        #pragma unroll
        for (int w = 0; w < NWARPS; w++) L += wl[w][tid];
        g_pl[pb + tid] = L;
    }

    // ---- Decoupled completion: last CTA for this (s, kv) combines ----
    __threadfence();            // make partials visible device-wide
    __syncthreads();
    if (tid == 0)
        is_last = (atomicAdd(&g_cnt[skv], 1) == np - 1) ? 1 : 0;
    __syncthreads();
    if (!is_last) return;
    __threadfence();            // acquire: see all CTAs' partials

    const size_t base = (size_t)skv * NP * GQ;
    float L0 = 0.f, L1 = 0.f, o0 = 0.f, o1 = 0.f;
    for (int pp = 0; pp < np; pp++) {
        const size_t i0 = base + (size_t)pp * GQ + g0;
        const size_t i1 = i0 + 2;
        L0 += g_pl[i0];
        L1 += g_pl[i1];
        o0 += g_pacc[i0 * HD + d];
        o1 += g_pacc[i1 * HD + d];
    }
    out[(size_t)(s * NUM_HEADS + kv * GQ + g0)     * HD + d] = o0 / L0;
    out[(size_t)(s * NUM_HEADS + kv * GQ + g0 + 2) * HD + d] = o1 / L1;

    if (tid == 0) g_cnt[skv] = 0;   // self-clean for next (graph) launch
}

extern "C" void kernel_launch(void* const* d_in, const int* in_sizes, int n_in,
                              void* d_out, int out_size) {
    const float* query       = (const float*)d_in[0];
    const float* key_cache   = (const float*)d_in[1];
    const float* value_cache = (const float*)d_in[2];
    const float* scale       = (const float*)d_in[4];
    const int*   block_tab   = (const int*)  d_in[5];
    const int*   seq_lens    = (const int*)  d_in[6];
    const float* alibi       = (const float*)d_in[9];
    float* out = (float*)d_out;

    paged_attn_kernel<<<NUM_SEQS * KVH * NP, NTHREADS>>>(
        query, key_cache, value_cache, scale, block_tab, seq_lens, alibi, out);
}

// round 13
// speedup vs baseline: 1.1899x; 1.1029x over previous
#include <cuda_runtime.h>
#include <math.h>
#include <stdint.h>

#define NUM_SEQS   64
#define NUM_HEADS  32
#define KVH        8
#define GQ         4      // query heads per kv head
#define HD         128    // head size
#define BS         16     // paged block size
#define MAXL       2048
#define MAXB       128    // max blocks per seq
#define PART       128    // tokens per split-KV partition
#define NP         (MAXL / PART)   // 16
#define CH         16     // tokens per pipeline chunk == paged block
#define NTHREADS   256
#define NWARPS     8
#define FULLMASK   0xffffffffu

// Split-KV scratch (device globals)
__device__ float g_pacc[NUM_SEQS * KVH * NP * GQ * HD];
__device__ float g_pl[NUM_SEQS * KVH * NP * GQ];
__device__ int   g_cnt[NUM_SEQS * KVH];    // zero-initialized; self-cleaning

struct AccState {
    float4 a0, a1, a2, a3;
    float  lsum;           // per-lane: sum of e for head (lane&3)
};

__device__ __forceinline__ void token_step(
    AccState& st, const float4 k4, const float4 v4,
    const float4 qr0, const float4 qr1, const float4 qr2, const float4 qr3,
    const float rel, const float slp_lane, const int lane)
{
    float p0 = qr0.x*k4.x + qr0.y*k4.y + qr0.z*k4.z + qr0.w*k4.w;
    float p1 = qr1.x*k4.x + qr1.y*k4.y + qr1.z*k4.z + qr1.w*k4.w;
    float p2 = qr2.x*k4.x + qr2.y*k4.y + qr2.z*k4.z + qr2.w*k4.w;
    float p3 = qr3.x*k4.x + qr3.y*k4.y + qr3.z*k4.z + qr3.w*k4.w;

    const bool b0 = (lane & 1);
    float x01 = b0 ? p1 : p0;
    float y01 = b0 ? p0 : p1;
    x01 += __shfl_xor_sync(FULLMASK, y01, 1);
    float x23 = b0 ? p3 : p2;
    float y23 = b0 ? p2 : p3;
    x23 += __shfl_xor_sync(FULLMASK, y23, 1);
    const bool b1 = (lane & 2);
    float x = b1 ? x23 : x01;
    float y = b1 ? x01 : x23;
    x += __shfl_xor_sync(FULLMASK, y, 2);
    x += __shfl_xor_sync(FULLMASK, x, 4);
    x += __shfl_xor_sync(FULLMASK, x, 8);
    x += __shfl_xor_sync(FULLMASK, x, 16);

    const float e = __expf(fmaf(slp_lane, rel, x));
    st.lsum += e;

    const float e0 = __shfl_sync(FULLMASK, e, 0);
    const float e1 = __shfl_sync(FULLMASK, e, 1);
    const float e2 = __shfl_sync(FULLMASK, e, 2);
    const float e3 = __shfl_sync(FULLMASK, e, 3);

    st.a0.x += e0*v4.x; st.a0.y += e0*v4.y; st.a0.z += e0*v4.z; st.a0.w += e0*v4.w;
    st.a1.x += e1*v4.x; st.a1.y += e1*v4.y; st.a1.z += e1*v4.z; st.a1.w += e1*v4.w;
    st.a2.x += e2*v4.x; st.a2.y += e2*v4.y; st.a2.z += e2*v4.z; st.a2.w += e2*v4.w;
    st.a3.x += e3*v4.x; st.a3.y += e3*v4.y; st.a3.z += e3*v4.z; st.a3.w += e3*v4.w;
}

__device__ __forceinline__ void cpa16(uint32_t dst, const void* src) {
    asm volatile("cp.async.cg.shared.global [%0], [%1], 16;" :: "r"(dst), "l"(src));
}
#define CPA_COMMIT() asm volatile("cp.async.commit_group;" ::: "memory")
#define CPA_WAIT(n)  asm volatile("cp.async.wait_group %0;" :: "n"(n) : "memory")

__global__ __launch_bounds__(NTHREADS)
void paged_attn_kernel(const float* __restrict__ q,
                       const float* __restrict__ kcache,
                       const float* __restrict__ vcache,
                       const float* __restrict__ scale_p,
                       const int*   __restrict__ btab,
                       const int*   __restrict__ seqlen,
                       const float* __restrict__ slopes,
                       float*       __restrict__ out)
{
    const int p    = blockIdx.x % NP;
    const int kv   = (blockIdx.x / NP) % KVH;
    const int s    = blockIdx.x / (NP * KVH);
    const int tid  = threadIdx.x;
    const int lane = tid & 31;
    const int warp = tid >> 5;

    const int len = seqlen[s];
    const int t0  = p * PART;
    if (t0 >= len) return;
    const int tmax = min(PART, len - t0);
    const int np   = (len + PART - 1) / PART;
    const float scale = scale_p[0];

    // kvbuf[buf][k=0/v=1][token][dim] : 2*2*16*128*4 = 32 KB.
    // After the pipeline, the first 16 KB are reused as the cross-warp
    // reduction buffer "red[NWARPS][GQ][HD]" (and stage Q at the start).
    __shared__ float  kvbuf[2][2][CH][HD];
    __shared__ float  wl[NWARPS][GQ];
    __shared__ int    blk[PART / BS];
    __shared__ size_t sbase[PART / BS];
    __shared__ int    is_last;

    float (*red)[GQ][HD] = (float (*)[GQ][HD]) &kvbuf[0][0][0][0];

    // Stage Q (scaled) into the aliased region, read to registers
    for (int i = tid; i < GQ * HD; i += NTHREADS)
        (&red[0][0][0])[i] = q[(s * NUM_HEADS + kv * GQ) * HD + i] * scale;
    const int nch = (tmax + BS - 1) >> 4;       // active blocks == chunks
    if (tid < nch) blk[tid] = btab[s * MAXB + (t0 >> 4) + tid];
    __syncthreads();

    const size_t kvbase   = (size_t)kv * BS * HD;
    const size_t kvstride = (size_t)KVH * BS * HD;
    if (tid < nch) sbase[tid] = (size_t)blk[tid] * kvstride + kvbase;

    const float4 qr0 = ((const float4*)&red[0][0][0])[lane];
    const float4 qr1 = ((const float4*)&red[0][1][0])[lane];
    const float4 qr2 = ((const float4*)&red[0][2][0])[lane];
    const float4 qr3 = ((const float4*)&red[0][3][0])[lane];
    __syncthreads();   // Q consumed; kvbuf free for the pipeline

    const float slp_lane = slopes[kv * GQ + (lane & 3)];
    const float relbase  = (float)(t0 - (len - 1));

    // chunk copier: whole 8 KB K block + 8 KB V block via cp.async (16 B/thread x2)
    auto copy_chunk = [&](int c, int buf) {
        const char* ksrc = (const char*)(kcache + sbase[c]);
        const char* vsrc = (const char*)(vcache + sbase[c]);
        uint32_t kdst = (uint32_t)__cvta_generic_to_shared(&kvbuf[buf][0][0][0]) + tid * 16;
        uint32_t vdst = (uint32_t)__cvta_generic_to_shared(&kvbuf[buf][1][0][0]) + tid * 16;
        cpa16(kdst,        ksrc + tid * 16);
        cpa16(kdst + 4096, ksrc + tid * 16 + 4096);
        cpa16(vdst,        vsrc + tid * 16);
        cpa16(vdst + 4096, vsrc + tid * 16 + 4096);
    };

    // Prologue: fill both buffers
    copy_chunk(0, 0); CPA_COMMIT();
    if (nch > 1) { copy_chunk(1, 1); CPA_COMMIT(); }

    AccState st;
    st.a0 = make_float4(0,0,0,0); st.a1 = make_float4(0,0,0,0);
    st.a2 = make_float4(0,0,0,0); st.a3 = make_float4(0,0,0,0);
    st.lsum = 0.f;

    for (int c = 0; c < nch; c++) {
        if (c + 1 < nch) { CPA_WAIT(1); } else { CPA_WAIT(0); }
        __syncthreads();

        const int b = c & 1;
        const int tl0 = c * CH + warp * 2;      // warp owns 2 adjacent tokens
        const int tl1 = tl0 + 1;
        if (tl0 < tmax) {
            const float4 k4 = ((const float4*)&kvbuf[b][0][warp*2][0])[lane];
            const float4 v4 = ((const float4*)&kvbuf[b][1][warp*2][0])[lane];
            token_step(st, k4, v4, qr0, qr1, qr2, qr3,
                       relbase + (float)tl0, slp_lane, lane);
        }
        if (tl1 < tmax) {
            const float4 k4 = ((const float4*)&kvbuf[b][0][warp*2+1][0])[lane];
            const float4 v4 = ((const float4*)&kvbuf[b][1][warp*2+1][0])[lane];
            token_step(st, k4, v4, qr0, qr1, qr2, qr3,
                       relbase + (float)tl1, slp_lane, lane);
        }
        __syncthreads();                        // chunk c consumed by all warps

        if (c + 2 < nch) { copy_chunk(c + 2, b); CPA_COMMIT(); }
    }

    // Cross-warp reduction in smem (red aliases kvbuf; pipeline is done).
    if (lane < GQ) wl[warp][lane] = st.lsum;
    ((float4*)&red[warp][0][0])[lane] = st.a0;
    ((float4*)&red[warp][1][0])[lane] = st.a1;
    ((float4*)&red[warp][2][0])[lane] = st.a2;
    ((float4*)&red[warp][3][0])[lane] = st.a3;
    __syncthreads();

    const int d  = tid & 127;
    const int g0 = tid >> 7;
    float r0 = 0.f, r1 = 0.f;
    #pragma unroll
    for (int w = 0; w < NWARPS; w++) {
        r0 += red[w][g0][d];
        r1 += red[w][g0 + 2][d];
    }

    const int    skv = s * KVH + kv;
    const size_t pb  = ((size_t)skv * NP + p) * GQ;
    g_pacc[(pb + g0)     * HD + d] = r0;
    g_pacc[(pb + g0 + 2) * HD + d] = r1;
    if (tid < GQ) {
        float L = 0.f;
        #pragma unroll
        for (int w = 0; w < NWARPS; w++) L += wl[w][tid];
        g_pl[pb + tid] = L;
    }

    // ---- Decoupled completion: last CTA for this (s, kv) combines ----
    __threadfence();
    __syncthreads();
    if (tid == 0)
        is_last = (atomicAdd(&g_cnt[skv], 1) == np - 1) ? 1 : 0;
    __syncthreads();
    if (!is_last) return;
    __threadfence();

    const size_t base = (size_t)skv * NP * GQ;
    float L0 = 0.f, L1 = 0.f, o0 = 0.f, o1 = 0.f;
    for (int pp = 0; pp < np; pp++) {
        const size_t i0 = base + (size_t)pp * GQ + g0;
        const size_t i1 = i0 + 2;
        L0 += g_pl[i0];
        L1 += g_pl[i1];
        o0 += g_pacc[i0 * HD + d];
        o1 += g_pacc[i1 * HD + d];
    }
    out[(size_t)(s * NUM_HEADS + kv * GQ + g0)     * HD + d] = o0 / L0;
    out[(size_t)(s * NUM_HEADS + kv * GQ + g0 + 2) * HD + d] = o1 / L1;

    if (tid == 0) g_cnt[skv] = 0;
}

extern "C" void kernel_launch(void* const* d_in, const int* in_sizes, int n_in,
                              void* d_out, int out_size) {
    const float* query       = (const float*)d_in[0];
    const float* key_cache   = (const float*)d_in[1];
    const float* value_cache = (const float*)d_in[2];
    const float* scale       = (const float*)d_in[4];
    const int*   block_tab   = (const int*)  d_in[5];
    const int*   seq_lens    = (const int*)  d_in[6];
    const float* alibi       = (const float*)d_in[9];
    float* out = (float*)d_out;

    paged_attn_kernel<<<NUM_SEQS * KVH * NP, NTHREADS>>>(
        query, key_cache, value_cache, scale, block_tab, seq_lens, alibi, out);
}

// round 14
// speedup vs baseline: 1.1903x; 1.0003x over previous
#include <cuda_runtime.h>
#include <math.h>
#include <stdint.h>

#define NUM_SEQS   64
#define NUM_HEADS  32
#define KVH        8
#define GQ         4      // query heads per kv head
#define HD         128    // head size
#define BS         16     // paged block size
#define MAXL       2048
#define MAXB       128    // max blocks per seq
#define PART       128    // tokens per split-KV partition
#define NP         (MAXL / PART)   // 16
#define CH         16     // tokens per pipeline chunk == paged block
#define NTHREADS   256
#define NWARPS     8
#define FULLMASK   0xffffffffu

// Split-KV scratch (device globals)
__device__ float g_pacc[NUM_SEQS * KVH * NP * GQ * HD];
__device__ float g_pl[NUM_SEQS * KVH * NP * GQ];
__device__ int   g_cnt[NUM_SEQS * KVH];    // zero-initialized; self-cleaning

// ---- packed f32x2 helpers (sm_103a FFMA2; PTX-only, ptxas won't auto-fuse) ----
__device__ __forceinline__ uint64_t pack2(float lo, float hi) {
    uint64_t r; asm("mov.b64 %0, {%1, %2};" : "=l"(r) : "f"(lo), "f"(hi)); return r;
}
__device__ __forceinline__ void unpack2(float& lo, float& hi, uint64_t v) {
    asm("mov.b64 {%0, %1}, %2;" : "=f"(lo), "=f"(hi) : "l"(v));
}
__device__ __forceinline__ uint64_t fma2(uint64_t a, uint64_t b, uint64_t c) {
    uint64_t d;
    asm("fma.rn.f32x2 %0, %1, %2, %3;" : "=l"(d) : "l"(a), "l"(b), "l"(c));
    return d;
}
__device__ __forceinline__ uint64_t mul2(uint64_t a, uint64_t b) {
    uint64_t d;
    asm("mul.rn.f32x2 %0, %1, %2;" : "=l"(d) : "l"(a), "l"(b));
    return d;
}

struct AccState {
    // packed accumulators: head g -> (lo: dims 4l+0,4l+1), (hi: dims 4l+2,4l+3)
    uint64_t a0lo, a0hi, a1lo, a1hi, a2lo, a2hi, a3lo, a3hi;
    float    lsum;        // per-lane: sum of e for head (lane&3)
};

// One token: packed dot for 4 heads -> transposed butterfly (lane l ends with
// the COMPLETE score of head l&3) -> single exp/lane -> broadcast -> packed V FMA.
__device__ __forceinline__ void token_step(
    AccState& st, const float4 k4, const float4 v4,
    const uint64_t q0lo, const uint64_t q0hi, const uint64_t q1lo, const uint64_t q1hi,
    const uint64_t q2lo, const uint64_t q2hi, const uint64_t q3lo, const uint64_t q3hi,
    const float rel, const float slp_lane, const int lane)
{
    const uint64_t klo = pack2(k4.x, k4.y);
    const uint64_t khi = pack2(k4.z, k4.w);

    // per-head packed dot: 2 FFMA2 + 1 FADD
    float p0, p1, p2, p3;
    {
        uint64_t t = fma2(q0hi, khi, mul2(q0lo, klo));
        float lo, hi; unpack2(lo, hi, t); p0 = lo + hi;
    }
    {
        uint64_t t = fma2(q1hi, khi, mul2(q1lo, klo));
        float lo, hi; unpack2(lo, hi, t); p1 = lo + hi;
    }
    {
        uint64_t t = fma2(q2hi, khi, mul2(q2lo, klo));
        float lo, hi; unpack2(lo, hi, t); p2 = lo + hi;
    }
    {
        uint64_t t = fma2(q3hi, khi, mul2(q3lo, klo));
        float lo, hi; unpack2(lo, hi, t); p3 = lo + hi;
    }

    const bool b0 = (lane & 1);
    float x01 = b0 ? p1 : p0;
    float y01 = b0 ? p0 : p1;
    x01 += __shfl_xor_sync(FULLMASK, y01, 1);
    float x23 = b0 ? p3 : p2;
    float y23 = b0 ? p2 : p3;
    x23 += __shfl_xor_sync(FULLMASK, y23, 1);
    const bool b1 = (lane & 2);
    float x = b1 ? x23 : x01;
    float y = b1 ? x01 : x23;
    x += __shfl_xor_sync(FULLMASK, y, 2);
    x += __shfl_xor_sync(FULLMASK, x, 4);
    x += __shfl_xor_sync(FULLMASK, x, 8);
    x += __shfl_xor_sync(FULLMASK, x, 16);

    const float e = __expf(fmaf(slp_lane, rel, x));
    st.lsum += e;

    const uint64_t e0p = pack2(__shfl_sync(FULLMASK, e, 0), __shfl_sync(FULLMASK, e, 0));
    const uint64_t e1p = pack2(__shfl_sync(FULLMASK, e, 1), __shfl_sync(FULLMASK, e, 1));
    const uint64_t e2p = pack2(__shfl_sync(FULLMASK, e, 2), __shfl_sync(FULLMASK, e, 2));
    const uint64_t e3p = pack2(__shfl_sync(FULLMASK, e, 3), __shfl_sync(FULLMASK, e, 3));

    const uint64_t vlo = pack2(v4.x, v4.y);
    const uint64_t vhi = pack2(v4.z, v4.w);

    st.a0lo = fma2(e0p, vlo, st.a0lo); st.a0hi = fma2(e0p, vhi, st.a0hi);
    st.a1lo = fma2(e1p, vlo, st.a1lo); st.a1hi = fma2(e1p, vhi, st.a1hi);
    st.a2lo = fma2(e2p, vlo, st.a2lo); st.a2hi = fma2(e2p, vhi, st.a2hi);
    st.a3lo = fma2(e3p, vlo, st.a3lo); st.a3hi = fma2(e3p, vhi, st.a3hi);
}

__device__ __forceinline__ void cpa16(uint32_t dst, const void* src) {
    asm volatile("cp.async.cg.shared.global [%0], [%1], 16;" :: "r"(dst), "l"(src));
}
#define CPA_COMMIT() asm volatile("cp.async.commit_group;" ::: "memory")
#define CPA_WAIT(n)  asm volatile("cp.async.wait_group %0;" :: "n"(n) : "memory")

__global__ __launch_bounds__(NTHREADS)
void paged_attn_kernel(const float* __restrict__ q,
                       const float* __restrict__ kcache,
                       const float* __restrict__ vcache,
                       const float* __restrict__ scale_p,
                       const int*   __restrict__ btab,
                       const int*   __restrict__ seqlen,
                       const float* __restrict__ slopes,
                       float*       __restrict__ out)
{
    const int p    = blockIdx.x % NP;
    const int kv   = (blockIdx.x / NP) % KVH;
    const int s    = blockIdx.x / (NP * KVH);
    const int tid  = threadIdx.x;
    const int lane = tid & 31;
    const int warp = tid >> 5;

    const int len = seqlen[s];
    const int t0  = p * PART;
    if (t0 >= len) return;
    const int tmax = min(PART, len - t0);
    const int np   = (len + PART - 1) / PART;
    const float scale = scale_p[0];

    // kvbuf: 3 buffers x (K block 8 KB + V block 8 KB) = 48 KB.
    // First 16 KB aliased as the reduction buffer red[NWARPS][GQ][HD]
    // (and Q staging) outside the pipeline.
    __shared__ float  kvbuf[3][2][CH][HD];
    __shared__ float  wl[NWARPS][GQ];
    __shared__ int    blk[PART / BS];
    __shared__ size_t sbase[PART / BS];
    __shared__ int    is_last;

    float (*red)[GQ][HD] = (float (*)[GQ][HD]) &kvbuf[0][0][0][0];

    for (int i = tid; i < GQ * HD; i += NTHREADS)
        (&red[0][0][0])[i] = q[(s * NUM_HEADS + kv * GQ) * HD + i] * scale;
    const int nch = (tmax + BS - 1) >> 4;
    if (tid < nch) blk[tid] = btab[s * MAXB + (t0 >> 4) + tid];
    __syncthreads();

    const size_t kvbase   = (size_t)kv * BS * HD;
    const size_t kvstride = (size_t)KVH * BS * HD;
    if (tid < nch) sbase[tid] = (size_t)blk[tid] * kvstride + kvbase;

    // packed Q registers (lane owns dims 4*lane .. 4*lane+3 per head)
    const float4 qr0 = ((const float4*)&red[0][0][0])[lane];
    const float4 qr1 = ((const float4*)&red[0][1][0])[lane];
    const float4 qr2 = ((const float4*)&red[0][2][0])[lane];
    const float4 qr3 = ((const float4*)&red[0][3][0])[lane];
    const uint64_t q0lo = pack2(qr0.x, qr0.y), q0hi = pack2(qr0.z, qr0.w);
    const uint64_t q1lo = pack2(qr1.x, qr1.y), q1hi = pack2(qr1.z, qr1.w);
    const uint64_t q2lo = pack2(qr2.x, qr2.y), q2hi = pack2(qr2.z, qr2.w);
    const uint64_t q3lo = pack2(qr3.x, qr3.y), q3hi = pack2(qr3.z, qr3.w);
    __syncthreads();   // Q consumed; kvbuf free for the pipeline

    const float slp_lane = slopes[kv * GQ + (lane & 3)];
    const float relbase  = (float)(t0 - (len - 1));

    auto copy_chunk = [&](int c, int buf) {
        const char* ksrc = (const char*)(kcache + sbase[c]);
        const char* vsrc = (const char*)(vcache + sbase[c]);
        uint32_t kdst = (uint32_t)__cvta_generic_to_shared(&kvbuf[buf][0][0][0]) + tid * 16;
        uint32_t vdst = (uint32_t)__cvta_generic_to_shared(&kvbuf[buf][1][0][0]) + tid * 16;
        cpa16(kdst,        ksrc + tid * 16);
        cpa16(kdst + 4096, ksrc + tid * 16 + 4096);
        cpa16(vdst,        vsrc + tid * 16);
        cpa16(vdst + 4096, vsrc + tid * 16 + 4096);
    };

    // Prologue: chunks 0 and 1 into buffers 0 and 1
    copy_chunk(0, 0); CPA_COMMIT();
    if (nch > 1) { copy_chunk(1, 1); CPA_COMMIT(); }

    AccState st;
    st.a0lo = st.a0hi = st.a1lo = st.a1hi = 0ull;
    st.a2lo = st.a2hi = st.a3lo = st.a3hi = 0ull;
    st.lsum = 0.f;

    // Single barrier per chunk: the sync at iter-c start also retires the
    // WAR hazard for buffer (c+2)%3 == (c-1)%3 (consumed at iter c-1).
    for (int c = 0; c < nch; c++) {
        if (c + 1 < nch) { CPA_WAIT(1); } else { CPA_WAIT(0); }
        __syncthreads();

        if (c + 2 < nch) { copy_chunk(c + 2, (c + 2) % 3); CPA_COMMIT(); }

        const int b = c % 3;
        const int tl0 = c * CH + warp * 2;
        const int tl1 = tl0 + 1;
        if (tl0 < tmax) {
            const float4 k4 = ((const float4*)&kvbuf[b][0][warp*2][0])[lane];
            const float4 v4 = ((const float4*)&kvbuf[b][1][warp*2][0])[lane];
            token_step(st, k4, v4, q0lo, q0hi, q1lo, q1hi, q2lo, q2hi, q3lo, q3hi,
                       relbase + (float)tl0, slp_lane, lane);
        }
        if (tl1 < tmax) {
            const float4 k4 = ((const float4*)&kvbuf[b][0][warp*2+1][0])[lane];
            const float4 v4 = ((const float4*)&kvbuf[b][1][warp*2+1][0])[lane];
            token_step(st, k4, v4, q0lo, q0hi, q1lo, q1hi, q2lo, q2hi, q3lo, q3hi,
                       relbase + (float)tl1, slp_lane, lane);
        }
    }
    __syncthreads();   // all compute done before red aliases kvbuf

    // Unpack accumulators and cross-warp reduce in smem.
    float4 a0, a1, a2, a3;
    unpack2(a0.x, a0.y, st.a0lo); unpack2(a0.z, a0.w, st.a0hi);
    unpack2(a1.x, a1.y, st.a1lo); unpack2(a1.z, a1.w, st.a1hi);
    unpack2(a2.x, a2.y, st.a2lo); unpack2(a2.z, a2.w, st.a2hi);
    unpack2(a3.x, a3.y, st.a3lo); unpack2(a3.z, a3.w, st.a3hi);

    if (lane < GQ) wl[warp][lane] = st.lsum;
    ((float4*)&red[warp][0][0])[lane] = a0;
    ((float4*)&red[warp][1][0])[lane] = a1;
    ((float4*)&red[warp][2][0])[lane] = a2;
    ((float4*)&red[warp][3][0])[lane] = a3;
    __syncthreads();

    const int d  = tid & 127;
    const int g0 = tid >> 7;
    float r0 = 0.f, r1 = 0.f;
    #pragma unroll
    for (int w = 0; w < NWARPS; w++) {
        r0 += red[w][g0][d];
        r1 += red[w][g0 + 2][d];
    }

    const int    skv = s * KVH + kv;
    const size_t pb  = ((size_t)skv * NP + p) * GQ;
    g_pacc[(pb + g0)     * HD + d] = r0;
    g_pacc[(pb + g0 + 2) * HD + d] = r1;
    if (tid < GQ) {
        float L = 0.f;
        #pragma unroll
        for (int w = 0; w < NWARPS; w++) L += wl[w][tid];
        g_pl[pb + tid] = L;
    }

    // ---- Decoupled completion: last CTA for this (s, kv) combines ----
    __threadfence();
    __syncthreads();
    if (tid == 0)
        is_last = (atomicAdd(&g_cnt[skv], 1) == np - 1) ? 1 : 0;
    __syncthreads();
    if (!is_last) return;
    __threadfence();

    const size_t base = (size_t)skv * NP * GQ;
    float L0 = 0.f, L1 = 0.f, o0 = 0.f, o1 = 0.f;
    for (int pp = 0; pp < np; pp++) {
        const size_t i0 = base + (size_t)pp * GQ + g0;
        const size_t i1 = i0 + 2;
        L0 += g_pl[i0];
        L1 += g_pl[i1];
        o0 += g_pacc[i0 * HD + d];
        o1 += g_pacc[i1 * HD + d];
    }
    out[(size_t)(s * NUM_HEADS + kv * GQ + g0)     * HD + d] = o0 / L0;
    out[(size_t)(s * NUM_HEADS + kv * GQ + g0 + 2) * HD + d] = o1 / L1;

    if (tid == 0) g_cnt[skv] = 0;
}

extern "C" void kernel_launch(void* const* d_in, const int* in_sizes, int n_in,
                              void* d_out, int out_size) {
    const float* query       = (const float*)d_in[0];
    const float* key_cache   = (const float*)d_in[1];
    const float* value_cache = (const float*)d_in[2];
    const float* scale       = (const float*)d_in[4];
    const int*   block_tab   = (const int*)  d_in[5];
    const int*   seq_lens    = (const int*)  d_in[6];
    const float* alibi       = (const float*)d_in[9];
    float* out = (float*)d_out;

    paged_attn_kernel<<<NUM_SEQS * KVH * NP, NTHREADS>>>(
        query, key_cache, value_cache, scale, block_tab, seq_lens, alibi, out);
}